// round 3
// baseline (speedup 1.0000x reference)
#include <cuda_runtime.h>
#include <math.h>

// Problem constants
#define Bq 512
#define Tt 10
#define Nn 50
#define Hh 200
#define Ee 10000
#define Rr 200
#define H3 600
#define BE (Bq*Ee)

// ---------------- scratch (static __device__, no allocations) ----------------
__device__ float g_proj_s[Ee*Hh];
__device__ float g_proj_o[Ee*Hh];
__device__ float g_bias_s[Bq*Hh];
__device__ float g_bias_o[Bq*Hh];
__device__ float g_seq_s[Bq*Tt*H3];
__device__ float g_seq_o[Bq*Tt*H3];
__device__ float g_gi_s[Bq*Tt*H3];
__device__ float g_gi_o[Bq*Tt*H3];
__device__ float g_gh_s[Bq*H3];
__device__ float g_gh_o[Bq*H3];
__device__ float g_h_s[Bq*Hh];
__device__ float g_h_o[Bq*Hh];
__device__ float g_feat_s[Bq*H3];
__device__ float g_feat_o[Bq*H3];
__device__ float g_lp0[Bq];
__device__ float g_lp1[Bq];
__device__ int   g_sidx[Bq];
__device__ int   g_oidx[Bq];

// ---------------- stable descending counting sort (argsort(-len)) ------------
__global__ void sort_kernel(const int* __restrict__ s_hlen, const int* __restrict__ o_hlen)
{
    if (threadIdx.x == 0) {
        int c = 0;
        for (int v = Tt; v >= 1; --v)
            for (int b = 0; b < Bq; ++b)
                if (s_hlen[b] == v) g_sidx[c++] = b;
    } else if (threadIdx.x == 1) {
        int c = 0;
        for (int v = Tt; v >= 1; --v)
            for (int b = 0; b < Bq; ++b)
                if (o_hlen[b] == v) g_oidx[c++] = b;
    }
}

__global__ void init_kernel()
{
    int i = blockIdx.x * blockDim.x + threadIdx.x;
    if (i < Bq*Hh) { g_h_s[i] = 0.f; g_h_o[i] = 0.f; }
}

// ---------------- generic fp32 GEMM: C[M,N] = A[M,K] @ W[N,K]^T (+bias) ------
// 64x64 block tile, 4x4 per thread, 256 threads, BK=16.
__global__ void gemm_abt(const float* __restrict__ A, int lda,
                         const float* __restrict__ W, int ldw,
                         const float* __restrict__ bias,
                         float* __restrict__ C, int ldc,
                         int M, int N, int K)
{
    __shared__ float As[16][68];
    __shared__ float Ws[16][68];
    const int tid = threadIdx.x;
    const int tx = tid & 15, ty = tid >> 4;
    const int bm = blockIdx.y * 64, bn = blockIdx.x * 64;

    float acc[4][4];
#pragma unroll
    for (int i = 0; i < 4; i++)
#pragma unroll
        for (int j = 0; j < 4; j++) acc[i][j] = 0.f;

    for (int k0 = 0; k0 < K; k0 += 16) {
#pragma unroll
        for (int l = 0; l < 4; l++) {
            int i = tid + l * 256;
            int m = i >> 4, k = i & 15;
            int gm = bm + m, gk = k0 + k;
            As[k][m] = (gm < M && gk < K) ? A[(size_t)gm * lda + gk] : 0.f;
            int gn = bn + m;
            Ws[k][m] = (gn < N && gk < K) ? W[(size_t)gn * ldw + gk] : 0.f;
        }
        __syncthreads();
#pragma unroll
        for (int k = 0; k < 16; k++) {
            float4 av = *reinterpret_cast<const float4*>(&As[k][ty << 2]);
            float4 bv = *reinterpret_cast<const float4*>(&Ws[k][tx << 2]);
            float a[4] = {av.x, av.y, av.z, av.w};
            float bb[4] = {bv.x, bv.y, bv.z, bv.w};
#pragma unroll
            for (int i = 0; i < 4; i++)
#pragma unroll
                for (int j = 0; j < 4; j++) acc[i][j] += a[i] * bb[j];
        }
        __syncthreads();
    }
#pragma unroll
    for (int i = 0; i < 4; i++) {
        int gm = bm + (ty << 2) + i;
        if (gm >= M) continue;
#pragma unroll
        for (int j = 0; j < 4; j++) {
            int gn = bn + (tx << 2) + j;
            if (gn < N)
                C[(size_t)gm * ldc + gn] = acc[i][j] + (bias ? bias[gn] : 0.f);
        }
    }
}

// ---------------- per-batch attention bias: ba + se@Ws^T + re@Wr^T -----------
__global__ void bias_kernel(const int* __restrict__ trip, int scol,
                            const float* __restrict__ ent,
                            const float* __restrict__ Wa,  // (H, 3H) row-major
                            const float* __restrict__ ba,
                            float* __restrict__ bias)
{
    int b = blockIdx.x;
    __shared__ float se[Hh], re[Hh];
    int tid = threadIdx.x;
    int sid = trip[b * 3 + scol], rid = trip[b * 3 + 1];
    for (int h = tid; h < Hh; h += 256) {
        se[h] = ent[(size_t)sid * Hh + h];
        re[h] = ent[(size_t)rid * Hh + h];
    }
    __syncthreads();
    for (int g = tid; g < Hh; g += 256) {
        const float* wrow = Wa + (size_t)g * H3;
        float acc = ba[g];
#pragma unroll 4
        for (int h = 0; h < Hh; h++)
            acc += se[h] * wrow[Hh + h] + re[h] * wrow[2 * Hh + h];
        bias[b * Hh + g] = acc;
    }
}

// ---------------- attention + softmax + weighted sum + seq assembly ----------
__global__ void attn_kernel(const int* __restrict__ neigh, const int* __restrict__ nlen,
                            const int* __restrict__ hlen, const int* __restrict__ trip,
                            int scol,
                            const float* __restrict__ ent, const float* __restrict__ rel,
                            const float* __restrict__ proj, const float* __restrict__ bias,
                            const float* __restrict__ v, float* __restrict__ seq)
{
    const int bt = blockIdx.x;
    const int b = bt / Tt, t = bt % Tt;
    __shared__ float s_bias[Hh], s_v[Hh];
    __shared__ float s_logit[Nn], s_w[Nn];
    __shared__ int s_nidx[Nn];
    const int tid = threadIdx.x;
    for (int g = tid; g < Hh; g += 256) { s_bias[g] = bias[b * Hh + g]; s_v[g] = v[g]; }
    for (int n = tid; n < Nn; n += 256) s_nidx[n] = neigh[((size_t)b * Tt + t) * Nn + n];
    __syncthreads();
    const int nl = nlen[b * Tt + t];
    const int warp = tid >> 5, lane = tid & 31;
    for (int n = warp; n < nl; n += 8) {
        const float* pr = proj + (size_t)s_nidx[n] * Hh;
        float acc = 0.f;
        for (int g = lane; g < Hh; g += 32)
            acc += tanhf(pr[g] + s_bias[g]) * s_v[g];
        for (int o = 16; o; o >>= 1) acc += __shfl_xor_sync(0xffffffffu, acc, o);
        if (lane == 0) s_logit[n] = acc;
    }
    __syncthreads();
    if (warp == 0) {
        float m = -3.4e38f;
        for (int n = lane; n < nl; n += 32) m = fmaxf(m, s_logit[n]);
        for (int o = 16; o; o >>= 1) m = fmaxf(m, __shfl_xor_sync(0xffffffffu, m, o));
        float s = 0.f;
        for (int n = lane; n < nl; n += 32) { float e = expf(s_logit[n] - m); s_w[n] = e; s += e; }
        for (int o = 16; o; o >>= 1) s += __shfl_xor_sync(0xffffffffu, s, o);
        float inv = 1.f / s;
        for (int n = lane; n < nl; n += 32) s_w[n] *= inv;
    }
    __syncthreads();
    const float msk = (t < hlen[b]) ? 1.f : 0.f;
    const int sid = trip[b * 3 + scol], rid = trip[b * 3 + 1];
    float* out = seq + ((size_t)b * Tt + t) * H3;
    for (int h = tid; h < Hh; h += 256) {
        float acc = 0.f;
        for (int n = 0; n < nl; n++) acc += s_w[n] * ent[(size_t)s_nidx[n] * Hh + h];
        out[h] = acc * msk;
        out[Hh + h] = ent[(size_t)sid * Hh + h] * msk;
        out[2 * Hh + h] = rel[(size_t)rid * Hh + h] * msk;
    }
}

// ---------------- GRU pointwise update (gh already = h@Whh^T + bhh) ----------
__global__ void gru_update(const float* __restrict__ gi, const float* __restrict__ gh,
                           float* __restrict__ h, const int* __restrict__ len, int t)
{
    int b = blockIdx.x;
    int j = threadIdx.x;
    if (j >= Hh) return;
    if (t >= len[b]) return;   // masked step: h unchanged
    const float* gib = gi + ((size_t)b * Tt + t) * H3;
    const float* ghb = gh + (size_t)b * H3;
    float ir = gib[j], iz = gib[Hh + j], inn = gib[2 * Hh + j];
    float hr = ghb[j], hz = ghb[Hh + j], hn = ghb[2 * Hh + j];
    float rg = 1.f / (1.f + expf(-(ir + hr)));
    float zg = 1.f / (1.f + expf(-(iz + hz)));
    float ng = tanhf(inn + rg * hn);
    float hp = h[(size_t)b * Hh + j];
    h[(size_t)b * Hh + j] = (1.f - zg) * ng + zg * hp;
}

// ---------------- final feature assembly (permuted by idx) -------------------
__global__ void feat_kernel(const int* __restrict__ trip, const int* __restrict__ idx,
                            int scol, const float* __restrict__ ent,
                            const float* __restrict__ rel, const float* __restrict__ h,
                            float* __restrict__ feat)
{
    int b = blockIdx.x;
    int p = idx[b];
    int sid = trip[p * 3 + scol], rid = trip[p * 3 + 1];
    for (int i = threadIdx.x; i < Hh; i += 256) {
        feat[(size_t)b * H3 + i]          = ent[(size_t)sid * Hh + i];
        feat[(size_t)b * H3 + Hh + i]     = h[(size_t)p * Hh + i];
        feat[(size_t)b * H3 + 2*Hh + i]   = rel[(size_t)rid * Hh + i];
    }
}

// ---------------- cross-entropy per-row log-prob of label --------------------
__global__ void ce_kernel(const float* __restrict__ pred, const int* __restrict__ trip,
                          const int* __restrict__ idx, int labcol, float* __restrict__ lp)
{
    int b = blockIdx.x;
    const float* row = pred + (size_t)b * Ee;
    int tid = threadIdx.x;
    int lane = tid & 31, warp = tid >> 5;
    __shared__ float sred[8];

    float m = -3.4e38f;
    for (int i = tid; i < Ee; i += 256) m = fmaxf(m, row[i]);
    for (int o = 16; o; o >>= 1) m = fmaxf(m, __shfl_xor_sync(0xffffffffu, m, o));
    if (lane == 0) sred[warp] = m;
    __syncthreads();
    if (tid == 0) {
        float mm = sred[0];
        for (int i = 1; i < 8; i++) mm = fmaxf(mm, sred[i]);
        sred[0] = mm;
    }
    __syncthreads();
    m = sred[0];
    __syncthreads();

    float s = 0.f;
    for (int i = tid; i < Ee; i += 256) s += expf(row[i] - m);
    for (int o = 16; o; o >>= 1) s += __shfl_xor_sync(0xffffffffu, s, o);
    if (lane == 0) sred[warp] = s;
    __syncthreads();
    if (tid == 0) {
        float st = 0.f;
        for (int i = 0; i < 8; i++) st += sred[i];
        int lab = trip[idx[b] * 3 + labcol];
        lp[b] = row[lab] - m - logf(st);
    }
}

// ---------------- finalize: loss + index outputs ------------------------------
__global__ void finalize_kernel(float* __restrict__ out)
{
    int tid = threadIdx.x;
    if (tid == 0) {
        double a = 0.0, c = 0.0;
        for (int b = 0; b < Bq; b++) { a += (double)g_lp0[b]; c += (double)g_lp1[b]; }
        out[0] = (float)(-(a / (double)Bq) - (c / (double)Bq));
    }
    for (int b = tid; b < Bq; b += blockDim.x) {
        out[1 + 2 * (size_t)BE + b]       = (float)g_oidx[b];
        out[1 + 2 * (size_t)BE + Bq + b]  = (float)g_sidx[b];
    }
}

// ---------------- host-side orchestration ------------------------------------
extern "C" void kernel_launch(void* const* d_in, const int* in_sizes, int n_in,
                              void* d_out, int out_size)
{
    const int*   trip     = (const int*)d_in[0];
    const int*   s_neigh  = (const int*)d_in[1];
    const int*   s_nlen   = (const int*)d_in[2];
    const int*   s_hlen   = (const int*)d_in[3];
    const int*   o_neigh  = (const int*)d_in[4];
    const int*   o_nlen   = (const int*)d_in[5];
    const int*   o_hlen   = (const int*)d_in[6];
    const float* ent      = (const float*)d_in[7];
    const float* rel      = (const float*)d_in[8];
    const float* attn_s_w = (const float*)d_in[9];
    const float* attn_s_b = (const float*)d_in[10];
    const float* v_s      = (const float*)d_in[11];
    const float* attn_o_w = (const float*)d_in[12];
    const float* attn_o_b = (const float*)d_in[13];
    const float* v_o      = (const float*)d_in[14];
    const float* sub_w_ih = (const float*)d_in[15];
    const float* sub_w_hh = (const float*)d_in[16];
    const float* sub_b_ih = (const float*)d_in[17];
    const float* sub_b_hh = (const float*)d_in[18];
    const float* ob_w_ih  = (const float*)d_in[19];
    const float* ob_w_hh  = (const float*)d_in[20];
    const float* ob_b_ih  = (const float*)d_in[21];
    const float* ob_b_hh  = (const float*)d_in[22];
    const float* lin_sub_w = (const float*)d_in[23];
    const float* lin_sub_b = (const float*)d_in[24];
    const float* lin_ob_w  = (const float*)d_in[25];
    const float* lin_ob_b  = (const float*)d_in[26];
    float* out = (float*)d_out;

    float *proj_s, *proj_o, *bias_s, *bias_o, *seq_s, *seq_o, *gi_s, *gi_o;
    float *gh_s, *gh_o, *h_s, *h_o, *feat_s, *feat_o, *lp0, *lp1;
    int *sidx, *oidx;
    cudaGetSymbolAddress((void**)&proj_s, g_proj_s);
    cudaGetSymbolAddress((void**)&proj_o, g_proj_o);
    cudaGetSymbolAddress((void**)&bias_s, g_bias_s);
    cudaGetSymbolAddress((void**)&bias_o, g_bias_o);
    cudaGetSymbolAddress((void**)&seq_s,  g_seq_s);
    cudaGetSymbolAddress((void**)&seq_o,  g_seq_o);
    cudaGetSymbolAddress((void**)&gi_s,   g_gi_s);
    cudaGetSymbolAddress((void**)&gi_o,   g_gi_o);
    cudaGetSymbolAddress((void**)&gh_s,   g_gh_s);
    cudaGetSymbolAddress((void**)&gh_o,   g_gh_o);
    cudaGetSymbolAddress((void**)&h_s,    g_h_s);
    cudaGetSymbolAddress((void**)&h_o,    g_h_o);
    cudaGetSymbolAddress((void**)&feat_s, g_feat_s);
    cudaGetSymbolAddress((void**)&feat_o, g_feat_o);
    cudaGetSymbolAddress((void**)&lp0,    g_lp0);
    cudaGetSymbolAddress((void**)&lp1,    g_lp1);
    cudaGetSymbolAddress((void**)&sidx,   g_sidx);
    cudaGetSymbolAddress((void**)&oidx,   g_oidx);

    // 1) stable descending argsort + h0 = 0
    sort_kernel<<<1, 32>>>(s_hlen, o_hlen);
    init_kernel<<<(Bq * Hh + 255) / 256, 256>>>();

    // 2) entity projections through Wn (attn weight cols [0:H))
    dim3 gProj((Hh + 63) / 64, (Ee + 63) / 64);
    gemm_abt<<<gProj, 256>>>(ent, Hh, attn_s_w, H3, nullptr, proj_s, Hh, Ee, Hh, Hh);
    gemm_abt<<<gProj, 256>>>(ent, Hh, attn_o_w, H3, nullptr, proj_o, Hh, Ee, Hh, Hh);

    // 3) per-batch bias terms (se@Ws^T + re@Wr^T + ba)
    bias_kernel<<<Bq, 256>>>(trip, 0, ent, attn_s_w, attn_s_b, bias_s);
    bias_kernel<<<Bq, 256>>>(trip, 2, ent, attn_o_w, attn_o_b, bias_o);

    // 4) attention + softmax + weighted neighbor sum + seq assembly
    attn_kernel<<<Bq * Tt, 256>>>(s_neigh, s_nlen, s_hlen, trip, 0, ent, rel,
                                  proj_s, bias_s, v_s, seq_s);
    attn_kernel<<<Bq * Tt, 256>>>(o_neigh, o_nlen, o_hlen, trip, 2, ent, rel,
                                  proj_o, bias_o, v_o, seq_o);

    // 5) GRU input gates for all timesteps at once
    dim3 gGi((H3 + 63) / 64, (Bq * Tt + 63) / 64);
    gemm_abt<<<gGi, 256>>>(seq_s, H3, sub_w_ih, H3, sub_b_ih, gi_s, H3, Bq * Tt, H3, H3);
    gemm_abt<<<gGi, 256>>>(seq_o, H3, ob_w_ih,  H3, ob_b_ih,  gi_o, H3, Bq * Tt, H3, H3);

    // 6) sequential GRU steps
    dim3 gGh((H3 + 63) / 64, (Bq + 63) / 64);
    for (int t = 0; t < Tt; t++) {
        gemm_abt<<<gGh, 256>>>(h_s, Hh, sub_w_hh, Hh, sub_b_hh, gh_s, H3, Bq, H3, Hh);
        gru_update<<<Bq, 256>>>(gi_s, gh_s, h_s, s_hlen, t);
        gemm_abt<<<gGh, 256>>>(h_o, Hh, ob_w_hh, Hh, ob_b_hh, gh_o, H3, Bq, H3, Hh);
        gru_update<<<Bq, 256>>>(gi_o, gh_o, h_o, o_hlen, t);
    }

    // 7) permuted feature assembly
    feat_kernel<<<Bq, 256>>>(trip, sidx, 0, ent, rel, h_s, feat_s);
    feat_kernel<<<Bq, 256>>>(trip, oidx, 2, ent, rel, h_o, feat_o);

    // 8) prediction GEMMs directly into d_out
    //    layout: [loss(1) | sub_pred(B*E) | ob_pred(B*E) | o_idx(B) | s_idx(B)]
    dim3 gPred((Ee + 63) / 64, (Bq + 63) / 64);
    gemm_abt<<<gPred, 256>>>(feat_s, H3, lin_sub_w, H3, lin_sub_b,
                             out + 1 + (size_t)BE, Ee, Bq, Ee, H3);   // ob_pred
    gemm_abt<<<gPred, 256>>>(feat_o, H3, lin_ob_w, H3, lin_ob_b,
                             out + 1, Ee, Bq, Ee, H3);                // sub_pred

    // 9) CE log-probs + finalize (deterministic fixed-order sum)
    ce_kernel<<<Bq, 256>>>(out + 1 + (size_t)BE, trip, sidx, 2, lp0); // ob_pred vs o[s_idx]
    ce_kernel<<<Bq, 256>>>(out + 1,              trip, oidx, 0, lp1); // sub_pred vs s[o_idx]
    finalize_kernel<<<1, 512>>>(out);
}